// round 16
// baseline (speedup 1.0000x reference)
#include <cuda_runtime.h>
#include <math_constants.h>

// MultiSimilarityLoss: sim_mat [8192,8192] f32, labels [8192] i64-or-i32 -> scalar f32
//
// R16 = R14 verbatim (u16 labels; deep 2x4 front-batched LDG.cs.128; 256thr x
// 32 elems; 32 KB smem value buffer; 3-kernel structure) with ONE change:
// __launch_bounds__(256,6) -> 6 CTAs / 48 warps per SM. R8's 6-CTA failure
// is de-confounded: u16 labels (16 KB) fit the remaining 30 KB L1, and the
// deep load batch is kept (R8 also shallowed loads, -6.6us per R13).
//
//  - Poison: same-labeled elements x = s - 4 (in [-5,-3]).
//    * min over ALL x == hardest positive (self always poisoned, negs >= -1).
//    * max over ALL x == hardest negative (poison can't win).
//  - u16 compare: q = pair ^ (ml|ml<<16); even elem same iff (q&0xFFFF)==0,
//    odd elem same iff q < 0x10000.
//  - Dense pass2: LDS.128 + 4x(FFMA + MUFU.EX2 + FSETP + @FADD).
//  - Pos-side exp in a rare branch (~1.5% of threads).

constexpr int BN        = 8192;
constexpr int NTHREADS  = 256;
constexpr int PER       = BN / NTHREADS;   // 32
constexpr int NVEC      = PER / 4;         // 8 float4 slots per thread
constexpr int NWARPS    = NTHREADS / 32;   // 8

constexpr float ONE_MEPS = 1.0f - 1e-5f;          // pos threshold on s
constexpr float POISON   = 4.0f;
constexpr float PB       = ONE_MEPS - POISON;     // poisoned pos boundary ~ -3.00001
// exp(40(s-0.5)) = exp2(x*K40 + C40)
constexpr float K40 = 57.706801635558536f;        //  40*log2(e)
constexpr float C40 = -28.853400817779268f;       // -20*log2(e)
// exp(-2(s-0.5)) with s = x+4  ->  exp2(x*KP + CP)
constexpr float KP  = -2.885390081777927f;        //  -2*log2(e)
constexpr float CP  = -10.098865286222744f;       //  -7*log2(e)

__device__ unsigned short g_labels16[BN];
__device__ float g_row_loss[BN];

__device__ __forceinline__ float ex2(float a) {
    float r;
    asm("ex2.approx.ftz.f32 %0, %1;" : "=f"(r) : "f"(a));
    return r;
}

// Streaming (evict-first) 128-bit load: touched exactly once.
__device__ __forceinline__ float4 ldcs4(const float4* p) {
    float4 r;
    asm("ld.global.cs.v4.f32 {%0,%1,%2,%3}, [%4];"
        : "=f"(r.x), "=f"(r.y), "=f"(r.z), "=f"(r.w) : "l"(p));
    return r;
}

// Dtype detection: odd 32-bit words are high halves (all zero, labels<1024) iff
// int64. 32 sampled words: P(false positive for int32) = (1/1024)^32 ~ 0.
__global__ __launch_bounds__(512) void prep_labels_kernel(const void* __restrict__ labels_raw) {
    const int tid = threadIdx.x;
    const unsigned* w = (const unsigned*)labels_raw;

    __shared__ int s_is64;
    if (tid < 32) {
        unsigned f = w[2 * tid + 1];
        unsigned any = __ballot_sync(0xffffffffu, f != 0u);
        if (tid == 0) s_is64 = (any == 0u) ? 1 : 0;
    }
    __syncthreads();

    int start = blockIdx.x * 512 + tid;
    if (s_is64) {
        const long long* l64 = (const long long*)labels_raw;
        for (int i = start; i < BN; i += 512 * 16) g_labels16[i] = (unsigned short)l64[i];
    } else {
        const int* l32 = (const int*)labels_raw;
        for (int i = start; i < BN; i += 512 * 16) g_labels16[i] = (unsigned short)l32[i];
    }
}

__global__ __launch_bounds__(NTHREADS, 6) void row_kernel(const float* __restrict__ sim)
{
    const int row  = blockIdx.x;
    const int tid  = threadIdx.x;
    const int lane = tid & 31;
    const int warp = tid >> 5;

    const unsigned ml  = (unsigned)__ldg(&g_labels16[row]);
    const unsigned pat = ml * 0x00010001u;             // ml in both u16 halves

    __shared__ float4 vsm[NVEC * NTHREADS];            // 32 KB poisoned values
    __shared__ float s_mn[NWARPS], s_mx[NWARPS];
    __shared__ float s_minall, s_maxneg;
    __shared__ float s_ps[NWARPS], s_ns[NWARPS];

    const float4* __restrict__ srow4 = reinterpret_cast<const float4*>(sim + (size_t)row * BN);
    const uint2*  __restrict__ labu  = reinterpret_cast<const uint2*>(g_labels16);
    // uint2 slot j4 covers labels/cols 4*j4 .. 4*j4+3, matching float4 slot j4.

    // ---- pass 1: 2 chunks of (4 sim float4 + 4 label uint2) front-batched ----
    float mn = CUDART_INF_F;    // min over all x == hardest positive (poisoned)
    float mx = -CUDART_INF_F;   // max over all x == hardest negative

    #pragma unroll
    for (int c = 0; c < 2; c++) {
        float4 a[4];
        uint2  b[4];
        #pragma unroll
        for (int k = 0; k < 4; k++) a[k] = ldcs4(srow4 + tid + (c * 4 + k) * NTHREADS);
        #pragma unroll
        for (int k = 0; k < 4; k++) b[k] = __ldg(labu + tid + (c * 4 + k) * NTHREADS);
        #pragma unroll
        for (int k = 0; k < 4; k++) {
            unsigned q0 = b[k].x ^ pat;
            unsigned q1 = b[k].y ^ pat;
            float x0 = a[k].x; if ((q0 & 0xFFFFu) == 0u) x0 -= POISON;  // even: low half
            float x1 = a[k].y; if (q0 < 0x10000u)        x1 -= POISON;  // odd: high half
            float x2 = a[k].z; if ((q1 & 0xFFFFu) == 0u) x2 -= POISON;
            float x3 = a[k].w; if (q1 < 0x10000u)        x3 -= POISON;
            mn = fminf(fminf(mn, fminf(x0, x1)), fminf(x2, x3));
            mx = fmaxf(fmaxf(mx, fmaxf(x0, x1)), fmaxf(x2, x3));
            vsm[(c * 4 + k) * NTHREADS + tid] = make_float4(x0, x1, x2, x3);
        }
    }
    const float my_mn = mn;                            // thread-local pos trigger

    // ---- block reduce min_all / max_neg ----
    #pragma unroll
    for (int o = 16; o; o >>= 1) {
        mn = fminf(mn, __shfl_xor_sync(0xffffffffu, mn, o));
        mx = fmaxf(mx, __shfl_xor_sync(0xffffffffu, mx, o));
    }
    if (lane == 0) { s_mn[warp] = mn; s_mx[warp] = mx; }
    __syncthreads();
    if (warp == 0) {
        float a = (lane < NWARPS) ? s_mn[lane] : CUDART_INF_F;
        float b = (lane < NWARPS) ? s_mx[lane] : -CUDART_INF_F;
        #pragma unroll
        for (int o = 4; o; o >>= 1) {
            a = fminf(a, __shfl_xor_sync(0xffffffffu, a, o));
            b = fmaxf(b, __shfl_xor_sync(0xffffffffu, b, o));
        }
        if (lane == 0) { s_minall = a; s_maxneg = b; }
    }
    __syncthreads();

    const float pb_up = __int_as_float(__float_as_int(PB) - 1);  // next float toward 0
    // Positive exists iff min_all < pb_up. Then hardest positive (poisoned) =
    // min_all, and sel_neg threshold tn = min_pos - 0.1 = min_all + 3.9.
    const float min_all = s_minall;
    const float tn = (min_all < pb_up) ? (min_all + 3.9f) : CUDART_INF_F;

    // ---- dense neg pass from smem: LDS.128 + 4x(FFMA+MUFU+FSETP+@FADD) ----
    float ns0 = 0.0f, ns1 = 0.0f, ns2 = 0.0f, ns3 = 0.0f;
    #pragma unroll
    for (int j = 0; j < NVEC; j++) {
        float4 x = vsm[j * NTHREADS + tid];
        float e0 = ex2(fmaf(x.x, K40, C40));
        float e1 = ex2(fmaf(x.y, K40, C40));
        float e2 = ex2(fmaf(x.z, K40, C40));
        float e3 = ex2(fmaf(x.w, K40, C40));
        if (x.x > tn) ns0 += e0;    // poisoned x <= -3 < tn always (tn >= -1.1)
        if (x.y > tn) ns1 += e1;
        if (x.z > tn) ns2 += e2;
        if (x.w > tn) ns3 += e3;
    }
    float neg_sum = (ns0 + ns1) + (ns2 + ns3);

    // ---- rare pos pass (this thread owns >= 1 positive) ----
    float pos_sum = 0.0f;
    if (my_mn < pb_up) {
        // sel_pos: x <= PB (positive) AND s - 0.1 < max_neg i.e. x < max_neg - 3.9
        float tp = fminf(pb_up, s_maxneg - 3.9f);
        #pragma unroll
        for (int j = 0; j < NVEC; j++) {
            float4 x = vsm[j * NTHREADS + tid];
            float e0 = ex2(fmaf(x.x, KP, CP));   // exp(-2(s-0.5)) on poisoned x
            float e1 = ex2(fmaf(x.y, KP, CP));
            float e2 = ex2(fmaf(x.z, KP, CP));
            float e3 = ex2(fmaf(x.w, KP, CP));
            if (x.x < tp) pos_sum += e0;
            if (x.y < tp) pos_sum += e1;
            if (x.z < tp) pos_sum += e2;
            if (x.w < tp) pos_sum += e3;
        }
    }

    // ---- block reduce the two sums ----
    #pragma unroll
    for (int o = 16; o; o >>= 1) {
        pos_sum += __shfl_xor_sync(0xffffffffu, pos_sum, o);
        neg_sum += __shfl_xor_sync(0xffffffffu, neg_sum, o);
    }
    if (lane == 0) { s_ps[warp] = pos_sum; s_ns[warp] = neg_sum; }
    __syncthreads();
    if (tid == 0) {
        float ps = 0.0f, ns = 0.0f;
        #pragma unroll
        for (int wi = 0; wi < NWARPS; wi++) { ps += s_ps[wi]; ns += s_ns[wi]; }
        float loss = 0.0f;
        if (ps > 0.0f && ns > 0.0f)      // exp > 0: ps>0 <=> any(sel_pos)
            loss = log1pf(ps) * 0.5f + log1pf(ns) * 0.025f;
        g_row_loss[row] = loss;
    }
}

__global__ __launch_bounds__(1024) void reduce_kernel(float* __restrict__ out) {
    int tid = threadIdx.x;
    float sum = 0.0f;
    #pragma unroll
    for (int i = 0; i < BN / 1024; i++) sum += g_row_loss[tid + i * 1024];
    __shared__ float s[32];
    #pragma unroll
    for (int o = 16; o; o >>= 1) sum += __shfl_xor_sync(0xffffffffu, sum, o);
    if ((tid & 31) == 0) s[tid >> 5] = sum;
    __syncthreads();
    if (tid < 32) {
        float x = s[tid];
        #pragma unroll
        for (int o = 16; o; o >>= 1) x += __shfl_xor_sync(0xffffffffu, x, o);
        if (tid == 0) out[0] = x / (float)BN;
    }
}

extern "C" void kernel_launch(void* const* d_in, const int* in_sizes, int n_in,
                              void* d_out, int out_size) {
    // Guard against input ordering: sim has BN*BN elements, labels BN.
    const void* p0 = d_in[0];
    const void* p1 = d_in[1];
    const float* sim;
    const void*  labels;
    if (in_sizes[0] == BN) { labels = p0; sim = (const float*)p1; }
    else                   { sim = (const float*)p0; labels = p1; }
    float* out = (float*)d_out;

    prep_labels_kernel<<<16, 512>>>(labels);
    row_kernel<<<BN, NTHREADS>>>(sim);
    reduce_kernel<<<1, 1024>>>(out);
}

// round 17
// speedup vs baseline: 1.2268x; 1.2268x over previous
#include <cuda_runtime.h>
#include <math_constants.h>

// MultiSimilarityLoss: sim_mat [8192,8192] f32, labels [8192] i64-or-i32 -> scalar f32
//
// R17 = R14 (the measured optimum: u16 labels; deep 2x4 front-batched
// LDG.cs.128; 256thr x 32 elems; 32 KB smem value buffer; 5 CTAs/SM;
// 3-kernel structure) + single-sync min/max block reduce: after the warp
// shfl stage, ALL threads read the 8 warp partials from smem and reduce
// locally, removing the warp-0 stage and its second barrier.
//
//  - Poison: same-labeled elements x = s - 4 (in [-5,-3]).
//    * min over ALL x == hardest positive (self always poisoned, negs >= -1).
//    * max over ALL x == hardest negative (poison can't win).
//  - u16 compare: q = pair ^ (ml|ml<<16); even elem same iff (q&0xFFFF)==0,
//    odd elem same iff q < 0x10000.
//  - Dense pass2: LDS.128 + 4x(FFMA + MUFU.EX2 + FSETP + @FADD).
//  - Pos-side exp in a rare branch (~1.5% of threads).

constexpr int BN        = 8192;
constexpr int NTHREADS  = 256;
constexpr int PER       = BN / NTHREADS;   // 32
constexpr int NVEC      = PER / 4;         // 8 float4 slots per thread
constexpr int NWARPS    = NTHREADS / 32;   // 8

constexpr float ONE_MEPS = 1.0f - 1e-5f;          // pos threshold on s
constexpr float POISON   = 4.0f;
constexpr float PB       = ONE_MEPS - POISON;     // poisoned pos boundary ~ -3.00001
// exp(40(s-0.5)) = exp2(x*K40 + C40)
constexpr float K40 = 57.706801635558536f;        //  40*log2(e)
constexpr float C40 = -28.853400817779268f;       // -20*log2(e)
// exp(-2(s-0.5)) with s = x+4  ->  exp2(x*KP + CP)
constexpr float KP  = -2.885390081777927f;        //  -2*log2(e)
constexpr float CP  = -10.098865286222744f;       //  -7*log2(e)

__device__ unsigned short g_labels16[BN];
__device__ float g_row_loss[BN];

__device__ __forceinline__ float ex2(float a) {
    float r;
    asm("ex2.approx.ftz.f32 %0, %1;" : "=f"(r) : "f"(a));
    return r;
}

// Streaming (evict-first) 128-bit load: touched exactly once.
__device__ __forceinline__ float4 ldcs4(const float4* p) {
    float4 r;
    asm("ld.global.cs.v4.f32 {%0,%1,%2,%3}, [%4];"
        : "=f"(r.x), "=f"(r.y), "=f"(r.z), "=f"(r.w) : "l"(p));
    return r;
}

// Dtype detection: odd 32-bit words are high halves (all zero, labels<1024) iff
// int64. 32 sampled words: P(false positive for int32) = (1/1024)^32 ~ 0.
__global__ __launch_bounds__(512) void prep_labels_kernel(const void* __restrict__ labels_raw) {
    const int tid = threadIdx.x;
    const unsigned* w = (const unsigned*)labels_raw;

    __shared__ int s_is64;
    if (tid < 32) {
        unsigned f = w[2 * tid + 1];
        unsigned any = __ballot_sync(0xffffffffu, f != 0u);
        if (tid == 0) s_is64 = (any == 0u) ? 1 : 0;
    }
    __syncthreads();

    int start = blockIdx.x * 512 + tid;
    if (s_is64) {
        const long long* l64 = (const long long*)labels_raw;
        for (int i = start; i < BN; i += 512 * 16) g_labels16[i] = (unsigned short)l64[i];
    } else {
        const int* l32 = (const int*)labels_raw;
        for (int i = start; i < BN; i += 512 * 16) g_labels16[i] = (unsigned short)l32[i];
    }
}

__global__ __launch_bounds__(NTHREADS, 5) void row_kernel(const float* __restrict__ sim)
{
    const int row  = blockIdx.x;
    const int tid  = threadIdx.x;
    const int lane = tid & 31;
    const int warp = tid >> 5;

    const unsigned ml  = (unsigned)__ldg(&g_labels16[row]);
    const unsigned pat = ml * 0x00010001u;             // ml in both u16 halves

    __shared__ float4 vsm[NVEC * NTHREADS];            // 32 KB poisoned values
    __shared__ float s_mn[NWARPS], s_mx[NWARPS];
    __shared__ float s_ps[NWARPS], s_ns[NWARPS];

    const float4* __restrict__ srow4 = reinterpret_cast<const float4*>(sim + (size_t)row * BN);
    const uint2*  __restrict__ labu  = reinterpret_cast<const uint2*>(g_labels16);
    // uint2 slot j4 covers labels/cols 4*j4 .. 4*j4+3, matching float4 slot j4.

    // ---- pass 1: 2 chunks of (4 sim float4 + 4 label uint2) front-batched ----
    float mn = CUDART_INF_F;    // min over all x == hardest positive (poisoned)
    float mx = -CUDART_INF_F;   // max over all x == hardest negative

    #pragma unroll
    for (int c = 0; c < 2; c++) {
        float4 a[4];
        uint2  b[4];
        #pragma unroll
        for (int k = 0; k < 4; k++) a[k] = ldcs4(srow4 + tid + (c * 4 + k) * NTHREADS);
        #pragma unroll
        for (int k = 0; k < 4; k++) b[k] = __ldg(labu + tid + (c * 4 + k) * NTHREADS);
        #pragma unroll
        for (int k = 0; k < 4; k++) {
            unsigned q0 = b[k].x ^ pat;
            unsigned q1 = b[k].y ^ pat;
            float x0 = a[k].x; if ((q0 & 0xFFFFu) == 0u) x0 -= POISON;  // even: low half
            float x1 = a[k].y; if (q0 < 0x10000u)        x1 -= POISON;  // odd: high half
            float x2 = a[k].z; if ((q1 & 0xFFFFu) == 0u) x2 -= POISON;
            float x3 = a[k].w; if (q1 < 0x10000u)        x3 -= POISON;
            mn = fminf(fminf(mn, fminf(x0, x1)), fminf(x2, x3));
            mx = fmaxf(fmaxf(mx, fmaxf(x0, x1)), fmaxf(x2, x3));
            vsm[(c * 4 + k) * NTHREADS + tid] = make_float4(x0, x1, x2, x3);
        }
    }
    const float my_mn = mn;                            // thread-local pos trigger

    // ---- single-sync block reduce: warp shfl -> smem -> all-thread local ----
    #pragma unroll
    for (int o = 16; o; o >>= 1) {
        mn = fminf(mn, __shfl_xor_sync(0xffffffffu, mn, o));
        mx = fmaxf(mx, __shfl_xor_sync(0xffffffffu, mx, o));
    }
    if (lane == 0) { s_mn[warp] = mn; s_mx[warp] = mx; }
    __syncthreads();
    float min_all = s_mn[0];
    float max_neg = s_mx[0];
    #pragma unroll
    for (int wi = 1; wi < NWARPS; wi++) {
        min_all = fminf(min_all, s_mn[wi]);   // broadcast LDS, conflict-free
        max_neg = fmaxf(max_neg, s_mx[wi]);
    }

    const float pb_up = __int_as_float(__float_as_int(PB) - 1);  // next float toward 0
    // Positive exists iff min_all < pb_up. Then hardest positive (poisoned) =
    // min_all, and sel_neg threshold tn = min_pos - 0.1 = min_all + 3.9.
    const float tn = (min_all < pb_up) ? (min_all + 3.9f) : CUDART_INF_F;

    // ---- dense neg pass from smem: LDS.128 + 4x(FFMA+MUFU+FSETP+@FADD) ----
    float ns0 = 0.0f, ns1 = 0.0f, ns2 = 0.0f, ns3 = 0.0f;
    #pragma unroll
    for (int j = 0; j < NVEC; j++) {
        float4 x = vsm[j * NTHREADS + tid];
        float e0 = ex2(fmaf(x.x, K40, C40));
        float e1 = ex2(fmaf(x.y, K40, C40));
        float e2 = ex2(fmaf(x.z, K40, C40));
        float e3 = ex2(fmaf(x.w, K40, C40));
        if (x.x > tn) ns0 += e0;    // poisoned x <= -3 < tn always (tn >= -1.1)
        if (x.y > tn) ns1 += e1;
        if (x.z > tn) ns2 += e2;
        if (x.w > tn) ns3 += e3;
    }
    float neg_sum = (ns0 + ns1) + (ns2 + ns3);

    // ---- rare pos pass (this thread owns >= 1 positive) ----
    float pos_sum = 0.0f;
    if (my_mn < pb_up) {
        // sel_pos: x <= PB (positive) AND s - 0.1 < max_neg i.e. x < max_neg - 3.9
        float tp = fminf(pb_up, max_neg - 3.9f);
        #pragma unroll
        for (int j = 0; j < NVEC; j++) {
            float4 x = vsm[j * NTHREADS + tid];
            float e0 = ex2(fmaf(x.x, KP, CP));   // exp(-2(s-0.5)) on poisoned x
            float e1 = ex2(fmaf(x.y, KP, CP));
            float e2 = ex2(fmaf(x.z, KP, CP));
            float e3 = ex2(fmaf(x.w, KP, CP));
            if (x.x < tp) pos_sum += e0;
            if (x.y < tp) pos_sum += e1;
            if (x.z < tp) pos_sum += e2;
            if (x.w < tp) pos_sum += e3;
        }
    }

    // ---- block reduce the two sums ----
    #pragma unroll
    for (int o = 16; o; o >>= 1) {
        pos_sum += __shfl_xor_sync(0xffffffffu, pos_sum, o);
        neg_sum += __shfl_xor_sync(0xffffffffu, neg_sum, o);
    }
    if (lane == 0) { s_ps[warp] = pos_sum; s_ns[warp] = neg_sum; }
    __syncthreads();
    if (tid == 0) {
        float ps = 0.0f, ns = 0.0f;
        #pragma unroll
        for (int wi = 0; wi < NWARPS; wi++) { ps += s_ps[wi]; ns += s_ns[wi]; }
        float loss = 0.0f;
        if (ps > 0.0f && ns > 0.0f)      // exp > 0: ps>0 <=> any(sel_pos)
            loss = log1pf(ps) * 0.5f + log1pf(ns) * 0.025f;
        g_row_loss[row] = loss;
    }
}

__global__ __launch_bounds__(1024) void reduce_kernel(float* __restrict__ out) {
    int tid = threadIdx.x;
    float sum = 0.0f;
    #pragma unroll
    for (int i = 0; i < BN / 1024; i++) sum += g_row_loss[tid + i * 1024];
    __shared__ float s[32];
    #pragma unroll
    for (int o = 16; o; o >>= 1) sum += __shfl_xor_sync(0xffffffffu, sum, o);
    if ((tid & 31) == 0) s[tid >> 5] = sum;
    __syncthreads();
    if (tid < 32) {
        float x = s[tid];
        #pragma unroll
        for (int o = 16; o; o >>= 1) x += __shfl_xor_sync(0xffffffffu, x, o);
        if (tid == 0) out[0] = x / (float)BN;
    }
}

extern "C" void kernel_launch(void* const* d_in, const int* in_sizes, int n_in,
                              void* d_out, int out_size) {
    // Guard against input ordering: sim has BN*BN elements, labels BN.
    const void* p0 = d_in[0];
    const void* p1 = d_in[1];
    const float* sim;
    const void*  labels;
    if (in_sizes[0] == BN) { labels = p0; sim = (const float*)p1; }
    else                   { sim = (const float*)p0; labels = p1; }
    float* out = (float*)d_out;

    prep_labels_kernel<<<16, 512>>>(labels);
    row_kernel<<<BN, NTHREADS>>>(sim);
    reduce_kernel<<<1, 1024>>>(out);
}